// round 15
// baseline (speedup 1.0000x reference)
#include <cuda_runtime.h>
#include <math_constants.h>

#define NB 96
#define ND 128
#define NPAIR (NB * NB)
#define NCLS 8
#define NUND 4560                 // NB*(NB-1)/2 undirected pairs
#define BTHR 1024
#define MAXBLK 160
#define POSC 4608                 // >= worst-case undirected pos (4560) + padding
#define FULLM 0xffffffffu

// ---------------- device scratch (no allocations allowed) ----------------
__device__ float g_Dm[NPAIR];                   // diag never read (masked everywhere)
__device__ float g_bP[MAXBLK], g_bN[MAXBLK];    // per-block pos/neg distance partials
__device__ float g_pQ[MAXBLK], g_pT[MAXBLK];
__device__ unsigned g_pQC[MAXBLK], g_pTC[MAXBLK];
__device__ volatile int g_flag[MAXBLK];         // kB done flags; block 0 resets

// =====================================================================
// Kernel A: distance matrix + per-block masked-sum partials.
// The graph edge to kB replaces the old spin barrier (and provides the
// memory ordering). No waits anywhere in this kernel.
// =====================================================================
__global__ void __launch_bounds__(BTHR, 1)
kA(const float* __restrict__ E, const void* __restrict__ labp) {
    __shared__ int   sLab[NB];
    __shared__ unsigned sOK[2];
    __shared__ float sF1[32], sF2[32];

    const int t = threadIdx.x;
    const int wid = t >> 5, lid = t & 31;
    const int bid = blockIdx.x;
    const int nblk = gridDim.x;

    // chain A (E): decode pair, issue row loads — label-independent
    const int p = bid * 32 + wid;
    const bool have = p < NUND;
    int pi = 0, pj = 1;
    float4 va = make_float4(0.f, 0.f, 0.f, 0.f), vb = va;
    if (have) {
        // decode undirected pair p -> (i, j), i < j ; offset(i) = i*(191-i)/2
        float s = sqrtf((float)(36481 - 8 * p));
        int i = (int)((191.0f - s) * 0.5f);
        while ((i + 1) * (191 - (i + 1)) / 2 <= p) ++i;
        while (i * (191 - i) / 2 > p) --i;
        pi = i; pj = i + 1 + (p - i * (191 - i) / 2);
        va = ((const float4*)(E + pi * ND))[lid];      // DRAM, in flight
        vb = ((const float4*)(E + pj * ND))[lid];
    }
    // chain B (labels) round 1: words 0..95 are safe for either layout;
    // int64 labels (values < 8) have zero high words => check words 2t+1, t<48.
    unsigned hiw = 0;
    if (t < 48) hiw = (unsigned)((const int*)labp)[2 * t + 1];
    if (wid < 2) {
        bool ok = (t < 48) ? (hiw == 0u) : true;
        unsigned m = __ballot_sync(FULLM, ok);
        if (lid == 0) sOK[wid] = m;
    }

    // distance + STG (stalls only on chain A)
    float dmv = 0.f;
    if (have) {
        float dx = va.x - vb.x, dy = va.y - vb.y, dz = va.z - vb.z, dw = va.w - vb.w;
        float d2 = dx * dx + dy * dy + dz * dz + dw * dw;
#pragma unroll
        for (int o = 16; o; o >>= 1) d2 += __shfl_down_sync(FULLM, d2, o);
        if (lid == 0) {
            dmv = sqrtf(fmaxf(d2, 0.f) + 1e-16f);
            g_Dm[pi * NB + pj] = dmv;
            g_Dm[pj * NB + pi] = dmv;
        }
    }

    // chain B round 2: resolve layout, load labels
    __syncthreads();
    const bool is64 = (sOK[0] == FULLM) && (sOK[1] == FULLM);
    if (t < NB) sLab[t] = is64 ? (int)((const long long*)labp)[t]
                               : ((const int*)labp)[t];
    __syncthreads();

    float myPos = 0.f, myNeg = 0.f;
    if (have && lid == 0) {
        if (sLab[pi] == sLab[pj]) myPos = dmv; else myNeg = dmv;
    }
    // residual pairs (only if the grid is unexpectedly small)
    for (int p2 = p + nblk * 32; p2 < NUND; p2 += nblk * 32) {
        float s = sqrtf((float)(36481 - 8 * p2));
        int i = (int)((191.0f - s) * 0.5f);
        while ((i + 1) * (191 - (i + 1)) / 2 <= p2) ++i;
        while (i * (191 - i) / 2 > p2) --i;
        int j = i + 1 + (p2 - i * (191 - i) / 2);
        const float4 a2 = ((const float4*)(E + i * ND))[lid];
        const float4 b2 = ((const float4*)(E + j * ND))[lid];
        float dx = a2.x - b2.x, dy = a2.y - b2.y, dz = a2.z - b2.z, dw = a2.w - b2.w;
        float d2 = dx * dx + dy * dy + dz * dz + dw * dw;
#pragma unroll
        for (int o = 16; o; o >>= 1) d2 += __shfl_down_sync(FULLM, d2, o);
        if (lid == 0) {
            float dm = sqrtf(fmaxf(d2, 0.f) + 1e-16f);
            g_Dm[i * NB + j] = dm;
            g_Dm[j * NB + i] = dm;
            if (sLab[i] == sLab[j]) myPos += dm; else myNeg += dm;
        }
    }
    if (lid == 0) { sF1[wid] = myPos; sF2[wid] = myNeg; }
    __syncthreads();
    if (t == 0) {
        float pS = 0.f, nS = 0.f;
#pragma unroll
        for (int w = 0; w < 32; w++) { pS += sF1[w]; nS += sF2[w]; }
        g_bP[bid] = pS; g_bN[bid] = nS;      // kernel boundary orders these
    }
}

// =====================================================================
// Kernel B: build + quad + triplet + combine. Labels and g_Dm are L2-warm.
// Only wait: block 0's done-flag poll (single-wave residency enforced).
// =====================================================================
__global__ void __launch_bounds__(BTHR, 1)
kB(float* __restrict__ out, const void* __restrict__ labp, int nA) {
    __shared__ __align__(16) float sPD[POSC];   // 18 KB
    __shared__ int   sPM[POSC];                 // 18 KB
    __shared__ int   sLab[NB];
    __shared__ unsigned sOK[2];
    __shared__ int   sRowCnt[NB];
    __shared__ int   sRowStart[NB];
    __shared__ int   sOff[NCLS + 1];
    __shared__ float sF1[32], sF2[32];
    __shared__ unsigned sC1[32], sC2[32];
    __shared__ float sThr;

    const int t = threadIdx.x;
    const int wid = t >> 5, lid = t & 31;
    const int bid = blockIdx.x;
    const int nblk = gridDim.x;
    if (nA > MAXBLK) nA = MAXBLK;               // cosmetic guard

    // label probe (L2-warm) + pad init
    unsigned hiw = 0;
    if (t < 48) hiw = (unsigned)((const int*)labp)[2 * t + 1];
    if (wid < 2) {
        bool ok = (t < 48) ? (hiw == 0u) : true;
        unsigned m = __ballot_sync(FULLM, ok);
        if (lid == 0) sOK[wid] = m;
    }
    for (int x = t; x < POSC; x += BTHR) { sPD[x] = -CUDART_INF_F; sPM[x] = 0; }
    __syncthreads();
    const bool is64 = (sOK[0] == FULLM) && (sOK[1] == FULLM);
    if (t < NB) sLab[t] = is64 ? (int)((const long long*)labp)[t]
                               : ((const int*)labp)[t];
    __syncthreads();

    // row-ballot pos counting: warp w owns rows w, w+32, w+64
#pragma unroll
    for (int rr = 0; rr < 3; rr++) {
        int r = wid + 32 * rr;
        int lr = sLab[r];
        int cnt = 0;
#pragma unroll
        for (int ch = 0; ch < 3; ch++) {
            int jj = ch * 32 + lid;
            unsigned m = __ballot_sync(FULLM, (jj > r) && (sLab[jj] == lr));
            cnt += __popc(m);
        }
        if (lid == 0) sRowCnt[r] = cnt;
    }
    __syncthreads();

    // warp 0: packed per-class scan + bases + thr
    if (wid == 0) {
        unsigned c0 = 0, c1 = 0, c2 = 0, c3 = 0;
#pragma unroll
        for (int ch = 0; ch < 3; ch++) {
            int r = ch * 32 + lid;
            int cnt = sRowCnt[r];
            int cr = sLab[r];
            unsigned f = (unsigned)cnt << ((cr & 1) * 16);
            unsigned p0 = ((cr >> 1) == 0) ? f : 0u;
            unsigned p1 = ((cr >> 1) == 1) ? f : 0u;
            unsigned p2 = ((cr >> 1) == 2) ? f : 0u;
            unsigned p3 = ((cr >> 1) == 3) ? f : 0u;
            unsigned i0 = p0, i1 = p1, i2 = p2, i3 = p3;
#pragma unroll
            for (int o = 1; o < 32; o <<= 1) {
                unsigned x0 = __shfl_up_sync(FULLM, i0, o);
                unsigned x1 = __shfl_up_sync(FULLM, i1, o);
                unsigned x2 = __shfl_up_sync(FULLM, i2, o);
                unsigned x3 = __shfl_up_sync(FULLM, i3, o);
                if (lid >= o) { i0 += x0; i1 += x1; i2 += x2; i3 += x3; }
            }
            unsigned e0 = i0 - p0 + c0, e1 = i1 - p1 + c1;
            unsigned e2 = i2 - p2 + c2, e3 = i3 - p3 + c3;
            unsigned sel = ((cr >> 1) == 0) ? e0 : ((cr >> 1) == 1) ? e1
                         : ((cr >> 1) == 2) ? e2 : e3;
            sRowCnt[r] = (int)((sel >> ((cr & 1) * 16)) & 0xFFFFu);
            c0 += __shfl_sync(FULLM, i0, 31);
            c1 += __shfl_sync(FULLM, i1, 31);
            c2 += __shfl_sync(FULLM, i2, 31);
            c3 += __shfl_sync(FULLM, i3, 31);
        }
        const int tt0 = (int)(c0 & 0xFFFFu), tt1 = (int)(c0 >> 16);
        const int tt2 = (int)(c1 & 0xFFFFu), tt3 = (int)(c1 >> 16);
        const int tt4 = (int)(c2 & 0xFFFFu), tt5 = (int)(c2 >> 16);
        const int tt6 = (int)(c3 & 0xFFFFu), tt7 = (int)(c3 >> 16);
        int bs0, bs1, bs2, bs3, bs4, bs5, bs6, bs7, b = 0;
        bs0 = b; b = (b + tt0 + 3) & ~3;  bs1 = b; b = (b + tt1 + 3) & ~3;
        bs2 = b; b = (b + tt2 + 3) & ~3;  bs3 = b; b = (b + tt3 + 3) & ~3;
        bs4 = b; b = (b + tt4 + 3) & ~3;  bs5 = b; b = (b + tt5 + 3) & ~3;
        bs6 = b; b = (b + tt6 + 3) & ~3;  bs7 = b; b = (b + tt7 + 3) & ~3;
        if (lid == 0) {
            sOff[0] = bs0; sOff[1] = bs1; sOff[2] = bs2; sOff[3] = bs3;
            sOff[4] = bs4; sOff[5] = bs5; sOff[6] = bs6; sOff[7] = bs7;
            sOff[8] = b;
        }
#pragma unroll
        for (int ch = 0; ch < 3; ch++) {
            int r = ch * 32 + lid;
            int cr = sLab[r];
            int bc = bs0;
            bc = (cr == 1) ? bs1 : bc;  bc = (cr == 2) ? bs2 : bc;
            bc = (cr == 3) ? bs3 : bc;  bc = (cr == 4) ? bs4 : bc;
            bc = (cr == 5) ? bs5 : bc;  bc = (cr == 6) ? bs6 : bc;
            bc = (cr == 7) ? bs7 : bc;
            sRowStart[r] = bc + sRowCnt[r];
        }
        // thr from kernel-A partials (L2-warm; deterministic order)
        float pS = 0.f, nS = 0.f;
        for (int x = lid; x < nA; x += 32) { pS += g_bP[x]; nS += g_bN[x]; }
#pragma unroll
        for (int o = 16; o; o >>= 1) {
            pS += __shfl_down_sync(FULLM, pS, o);
            nS += __shfl_down_sync(FULLM, nS, o);
        }
        if (lid == 0) {
            int nposU = tt0 + tt1 + tt2 + tt3 + tt4 + tt5 + tt6 + tt7;
            float cpos = 2.f * (float)nposU;
            float cneg = (float)(NPAIR - NB) - cpos;
            float mu = (cpos > 0.f && cneg > 0.f)
                       ? ((2.f * nS) / cneg - (2.f * pS) / cpos) : 0.f;
            sThr = fmaxf(mu, 0.f);
        }
    }
    __syncthreads();
    const int base8 = sOff[NCLS];

    // ballot scatter (g_Dm is L2-warm)
#pragma unroll
    for (int rr = 0; rr < 3; rr++) {
        int r = wid + 32 * rr;
        int lr = sLab[r];
        int run = sRowStart[r];
#pragma unroll
        for (int ch = 0; ch < 3; ch++) {
            int jj = ch * 32 + lid;
            bool pred = (jj > r) && (sLab[jj] == lr);
            unsigned m = __ballot_sync(FULLM, pred);
            if (pred) {
                int slot = run + __popc(m & ((1u << lid) - 1u));
                sPD[slot] = g_Dm[r * NB + jj];
                sPM[slot] = r | (jj << 8) | (lr << 16);
            }
            run += __popc(m);
        }
    }
    __syncthreads();

    const float thr = sThr, thrh = 0.5f * thr;

    // quad (undirected neg, weighted) + triplet
    float qs = 0.f, ts = 0.f; unsigned qc = 0, tc = 0;
    const int gt = bid * BTHR + t;
    const int GT = nblk * BTHR;

    const int qTot = NPAIR * NCLS * 4;
    for (int e = gt; e < qTot; e += GT) {
        int idx = e >> 5;
        int ii = idx / NB, jj = idx - ii * NB;
        if (ii >= jj) continue;
        int li = sLab[ii], lj = sLab[jj];
        if (li == lj) continue;
        float b = g_Dm[idx];
        int seg = (e >> 2) & 7, quar = e & 3;
        int lo = sOff[seg], hi = sOff[seg + 1];
        int qlen = ((hi - lo + 15) >> 4) << 2;
        int xs = lo + quar * qlen;
        int xe = min(xs + qlen, hi);
        int wi = 2 - (seg == li) - (seg == lj);
        float ls = 0.f; int lc = 0;
        for (int x = xs; x < xe; x += 4) {
            const float4 v = *reinterpret_cast<const float4*>(&sPD[x]);
            float d0 = b - v.x, d1 = b - v.y, d2 = b - v.z, d3 = b - v.w;
            if (d0 < thrh) { lc++; ls += fmaxf(d0, 0.f); }
            if (d1 < thrh) { lc++; ls += fmaxf(d1, 0.f); }
            if (d2 < thrh) { lc++; ls += fmaxf(d2, 0.f); }
            if (d3 < thrh) { lc++; ls += fmaxf(d3, 0.f); }
        }
        qs = fmaf((float)wi, ls, qs);
        qc += (unsigned)(wi * lc);
    }

    for (int e = gt; e < base8 * NB; e += GT) {
        int pp = e / NB, k = e - pp * NB;
        int meta = sPM[pp];
        int ai = meta & 255, aj = (meta >> 8) & 255, c = meta >> 16;
        float dij = sPD[pp];                       // -INF pads => skipped
        if (sLab[k] != c) {
            float tv1 = g_Dm[ai * NB + k] - dij;
            float tv2 = g_Dm[aj * NB + k] - dij;
            if (tv1 < thr) { tc++; ts += fmaxf(tv1, 0.f); }
            if (tv2 < thr) { tc++; ts += fmaxf(tv2, 0.f); }
        }
    }

    // block reduce, publish, combine
#pragma unroll
    for (int o = 16; o; o >>= 1) {
        qs += __shfl_down_sync(FULLM, qs, o);
        ts += __shfl_down_sync(FULLM, ts, o);
        qc += __shfl_down_sync(FULLM, qc, o);
        tc += __shfl_down_sync(FULLM, tc, o);
    }
    if ((t & 31) == 0) { sF1[wid] = qs; sF2[wid] = ts; sC1[wid] = qc; sC2[wid] = tc; }
    __syncthreads();
    if (t == 0) {
        float a = 0.f, b2 = 0.f; unsigned u1 = 0, u2 = 0;
#pragma unroll
        for (int w = 0; w < 32; w++) { a += sF1[w]; b2 += sF2[w]; u1 += sC1[w]; u2 += sC2[w]; }
        g_pQ[bid] = a; g_pT[bid] = b2; g_pQC[bid] = u1; g_pTC[bid] = u2;
        __threadfence();
        g_flag[bid] = 1;                           // done
    }
    if (bid != 0) return;

    if (wid == 0) {
        for (;;) {
            int ok = 1;
            for (int x = lid; x < nblk; x += 32) ok &= (g_flag[x] == 1);
            if (__ballot_sync(FULLM, ok) == FULLM) break;
        }
        __threadfence();
        float a = 0.f, b2 = 0.f; unsigned u1 = 0, u2 = 0;
        for (int x = lid; x < nblk; x += 32) {
            a += g_pQ[x]; b2 += g_pT[x]; u1 += g_pQC[x]; u2 += g_pTC[x];
        }
#pragma unroll
        for (int o = 16; o; o >>= 1) {
            a  += __shfl_down_sync(FULLM, a, o);
            b2 += __shfl_down_sync(FULLM, b2, o);
            u1 += __shfl_down_sync(FULLM, u1, o);
            u2 += __shfl_down_sync(FULLM, u2, o);
        }
        if (lid == 0) {
            float tl = (u2 > 0) ? b2 / (float)u2 : 0.f;
            float ql = (u1 > 0) ? a / (float)u1 : 0.f;
            out[0] = tl + ql;
        }
        for (int x = lid; x < MAXBLK; x += 32) g_flag[x] = 0;   // reset for replay
    }
}

extern "C" void kernel_launch(void* const* d_in, const int* in_sizes, int n_in,
                              void* d_out, int out_size) {
    const float* E = (const float*)d_in[0];
    const void* lab = d_in[1];
    (void)in_sizes; (void)n_in; (void)out_size;
    int sms = 148;
    cudaDeviceGetAttribute(&sms, cudaDevAttrMultiProcessorCount, 0);
    int grid = sms < MAXBLK ? sms : MAXBLK;
    // kB's done-flag tail requires single-wave residency
    int perSM = 1;
    cudaOccupancyMaxActiveBlocksPerMultiprocessor(&perSM, kB, BTHR, 0);
    if (perSM < 1) perSM = 1;
    long cap = (long)perSM * sms;
    if (grid > cap) grid = (int)cap;
    if (grid < 1) grid = 1;
    kA<<<grid, BTHR>>>(E, lab);
    kB<<<grid, BTHR>>>((float*)d_out, lab, grid);
}